// round 13
// baseline (speedup 1.0000x reference)
#include <cuda_runtime.h>
#include <cuda_bf16.h>
#include <cstdint>

#define Bn 16
#define Cn 512
#define Hn 64
#define Wn 64
#define Rn 64
#define A_LD 72    // bf16 row stride for A (144B)
#define GB_LD 264  // bf16 row stride for B tile (528B = 33x16B, conflict-free)

typedef unsigned long long ull;

// Scratch (device globals; no allocation allowed)
__device__ float g_sumC[Bn*Cn];
__device__ float g_partW[Bn*Cn*Wn];
__device__ float g_partH[Bn*Cn*Hn];
__device__ float g_wout[Bn*Rn*Wn];  // [b][r][w]
__device__ float g_hout[Bn*Rn*Hn];  // [b][r][h]
__device__ __align__(16) __nv_bfloat16 g_cp[(size_t)Bn*Cn*Hn*Wn];  // logits bf16
__device__ float g_psum[4*Bn*Hn*Wn];  // partial exp-sums [cT][b][h][w]

__device__ __forceinline__ unsigned s2u(const void* p) {
    return (unsigned)__cvta_generic_to_shared(p);
}

// ---------------------------------------------------------------------------
// K1: per-(b,c) plane reductions
// ---------------------------------------------------------------------------
__global__ __launch_bounds__(256) void k_reduce(const float* __restrict__ x) {
    int plane = blockIdx.x;
    const float4* x4 = (const float4*)(x + (size_t)plane * 4096);
    int tid = threadIdx.x;

    __shared__ float4 s4[256];
    __shared__ float  sh[256][4];

    float4 wacc = make_float4(0.f, 0.f, 0.f, 0.f);
    float hacc[4];
#pragma unroll
    for (int k = 0; k < 4; k++) {
        float4 f = x4[tid + 256 * k];
        wacc.x += f.x; wacc.y += f.y; wacc.z += f.z; wacc.w += f.w;
        hacc[k] = f.x + f.y + f.z + f.w;
    }
    s4[tid] = wacc;
    sh[tid][0] = hacc[0]; sh[tid][1] = hacc[1];
    sh[tid][2] = hacc[2]; sh[tid][3] = hacc[3];
    __syncthreads();

    if (tid < 16) {
        float4 t = s4[tid];
#pragma unroll
        for (int j = 1; j < 16; j++) {
            float4 u = s4[tid + 16 * j];
            t.x += u.x; t.y += u.y; t.z += u.z; t.w += u.w;
        }
        ((float4*)g_partW)[plane * 16 + tid] = t;
        s4[tid] = t;
    }
    if (tid >= 64 && tid < 128) {
        int h = tid - 64;
        int base = (h & 15) * 16;
        int k = h >> 4;
        float s = 0.f;
#pragma unroll
        for (int j = 0; j < 16; j++) s += sh[base + j][k];
        g_partH[plane * 64 + h] = s;
    }
    __syncthreads();
    if (tid == 0) {
        float tot = 0.f;
#pragma unroll
        for (int j = 0; j < 16; j++) {
            float4 u = s4[j];
            tot += u.x + u.y + u.z + u.w;
        }
        g_sumC[plane] = tot;
    }
}

// ---------------------------------------------------------------------------
// K2: gap reductions + 3-tap branch conv + PReLU -> g_wout / g_hout.
// ---------------------------------------------------------------------------
__global__ __launch_bounds__(256) void k_gap2(
    const float* __restrict__ w_w, const float* __restrict__ a_w,
    const float* __restrict__ w_h, const float* __restrict__ a_h) {
    int b = blockIdx.x, sel = blockIdx.y;
    int tid = threadIdx.x;
    int w = tid & 63, part = tid >> 6;

    __shared__ float red[4][64];
    __shared__ float g[66];

    const float* src = sel ? g_partH : g_partW;
    const float* p = src + ((size_t)(b * 512 + part * 128)) * 64 + w;
    float s = 0.f;
#pragma unroll 8
    for (int c = 0; c < 128; c++) s += p[c * 64];
    red[part][w] = s;
    if (tid == 64 + 0) g[0] = 0.f;
    if (tid == 64 + 1) g[65] = 0.f;
    __syncthreads();
    if (tid < 64)
        g[tid + 1] = (red[0][tid] + red[1][tid] + red[2][tid] + red[3][tid]) * (1.f / 32768.f);
    __syncthreads();

    const float* wt = sel ? w_h : w_w;
    float av = sel ? a_h[0] : a_w[0];
    float* dst = (sel ? g_hout : g_wout) + (size_t)b * 4096;
    for (int i = tid; i < 4096; i += 256) {
        int r = i >> 6, w2 = i & 63;
        float v = wt[r * 3] * g[w2] + wt[r * 3 + 1] * g[w2 + 1] + wt[r * 3 + 2] * g[w2 + 2];
        dst[i] = (v >= 0.f) ? v : av * v;
    }
}

// ---------------------------------------------------------------------------
// K3: tiled MMA (A built in-block from g_sumC + w_c), cp smem-staged ->
// coalesced stores, partial exp-sums.
// ---------------------------------------------------------------------------
#define GE_A    0        // bf16 [128][A_LD] = 18432 (A, then cp staging)
#define GE_B    18432    // bf16 [64][GB_LD] = 33792
#define GE_WO   52224    // f32 [64][64] = 16384 ; reused as wred
#define GE_HO   68608    // f32 [64][4]  = 1024
#define GE_GC   69632    // f32 [132]
#define GE_WC   70160    // f32 [192]
#define GE_BYTES 71168

__global__ void __launch_bounds__(256) k_gemmE(
    const float* __restrict__ w_c, const float* __restrict__ a_c) {
    extern __shared__ char sm[];
    int cT = blockIdx.x, h0 = blockIdx.y * 4, b = blockIdx.z;
    int tid = threadIdx.x;
    int lane = tid & 31, wid = tid >> 5;

    float* wo_s = (float*)(sm + GE_WO);
    float* ho_s = (float*)(sm + GE_HO);
    float* gcs  = (float*)(sm + GE_GC);
    float* wcs  = (float*)(sm + GE_WC);

    {
        const float* sumC = g_sumC + b * 512;
        for (int i = tid; i < 130; i += 256) {
            int cg = cT * 128 - 1 + i;
            gcs[i] = ((unsigned)cg < 512u) ? sumC[cg] * (1.f / 4096.f) : 0.f;
        }
        if (tid < 192) wcs[tid] = w_c[tid];
        const float4* wsrc = (const float4*)(g_wout + (size_t)b * 4096);
        float4* wdst = (float4*)wo_s;
        for (int i = tid; i < 1024; i += 256) wdst[i] = wsrc[i];
        int r = tid >> 2, hh = tid & 3;
        ho_s[tid] = g_hout[(size_t)b * 4096 + r * 64 + h0 + hh];
    }
    __syncthreads();

    // build A tile bf16 [128 c][64 r] with PReLU
    {
        float av = a_c[0];
        __nv_bfloat16* A = (__nv_bfloat16*)(sm + GE_A);
        for (int i = tid; i < 4096; i += 256) {
            int c = i >> 5, r2 = (i & 31) * 2;
            float g0 = gcs[c], g1 = gcs[c + 1], g2 = gcs[c + 2];
            float v0 = wcs[r2 * 3] * g0 + wcs[r2 * 3 + 1] * g1 + wcs[r2 * 3 + 2] * g2;
            float v1 = wcs[r2 * 3 + 3] * g0 + wcs[r2 * 3 + 4] * g1 + wcs[r2 * 3 + 5] * g2;
            v0 = (v0 >= 0.f) ? v0 : av * v0;
            v1 = (v1 >= 0.f) ? v1 : av * v1;
            *(__nv_bfloat162*)(A + c * A_LD + r2) = __floats2bfloat162_rn(v0, v1);
        }
    }
    __syncthreads();

    // hoist A fragments (A smem dead afterwards)
    unsigned afr[4][4];
    {
        unsigned aBase = s2u(sm + GE_A);
        int cb = wid * 16;
        int aRow = lane & 15;
        unsigned aColOff = (unsigned)(lane >> 4) * 16u;
#pragma unroll
        for (int ks = 0; ks < 4; ks++) {
            unsigned ad = aBase + (unsigned)((cb + aRow) * A_LD + ks * 16) * 2u + aColOff;
            asm volatile("ldmatrix.sync.aligned.m8n8.x4.shared.b16 {%0,%1,%2,%3}, [%4];\n"
                         : "=r"(afr[ks][0]), "=r"(afr[ks][1]),
                           "=r"(afr[ks][2]), "=r"(afr[ks][3])
                         : "r"(ad));
        }
    }

    // build B once: B[r][hj*64+w] = ho[r][hj] * wo[r][w]
    {
        __nv_bfloat16* B = (__nv_bfloat16*)(sm + GE_B);
        for (int i = tid; i < 8192; i += 256) {
            int r = i >> 7, col = (i & 127) * 2;
            int hj = col >> 6, w = col & 63;
            float hv = ho_s[r * 4 + hj];
            *(__nv_bfloat162*)(B + r * GB_LD + col) =
                __floats2bfloat162_rn(hv * wo_s[r * 64 + w], hv * wo_s[r * 64 + w + 1]);
        }
    }
    __syncthreads();

    float* wred = wo_s;  // reuse (wo dead after B build)
    unsigned sBase = s2u(sm + GE_B);
    int bRowOff = (lane & 7) + ((lane & 8) ? 8 : 0);
    int bColOff = (lane & 16) ? 8 : 0;

    for (int hj = 0; hj < 4; hj++) {
        int h = h0 + hj;
        float acc[8][4];
#pragma unroll
        for (int t = 0; t < 8; t++)
#pragma unroll
            for (int q = 0; q < 4; q++) acc[t][q] = 0.f;

#pragma unroll
        for (int ks = 0; ks < 4; ks++) {
            int k0 = ks * 16;
#pragma unroll
            for (int nb = 0; nb < 4; nb++) {
                unsigned bd = sBase +
                    (unsigned)((k0 + bRowOff) * GB_LD + hj * 64 + nb * 16 + bColOff) * 2u;
                unsigned bq0, bq1, bq2, bq3;
                asm volatile("ldmatrix.sync.aligned.m8n8.x4.trans.shared.b16 {%0,%1,%2,%3}, [%4];\n"
                             : "=r"(bq0), "=r"(bq1), "=r"(bq2), "=r"(bq3) : "r"(bd));
                asm volatile(
                    "mma.sync.aligned.m16n8k16.row.col.f32.bf16.bf16.f32 "
                    "{%0,%1,%2,%3},{%4,%5,%6,%7},{%8,%9},{%0,%1,%2,%3};\n"
                    : "+f"(acc[2 * nb][0]), "+f"(acc[2 * nb][1]),
                      "+f"(acc[2 * nb][2]), "+f"(acc[2 * nb][3])
                    : "r"(afr[ks][0]), "r"(afr[ks][1]), "r"(afr[ks][2]), "r"(afr[ks][3]),
                      "r"(bq0), "r"(bq1));
                asm volatile(
                    "mma.sync.aligned.m16n8k16.row.col.f32.bf16.bf16.f32 "
                    "{%0,%1,%2,%3},{%4,%5,%6,%7},{%8,%9},{%0,%1,%2,%3};\n"
                    : "+f"(acc[2 * nb + 1][0]), "+f"(acc[2 * nb + 1][1]),
                      "+f"(acc[2 * nb + 1][2]), "+f"(acc[2 * nb + 1][3])
                    : "r"(afr[ks][0]), "r"(afr[ks][1]), "r"(afr[ks][2]), "r"(afr[ks][3]),
                      "r"(bq2), "r"(bq3));
            }
        }

        // stage cp tile into dead A region (144B row stride)
        {
            int c_loc = wid * 16 + (lane >> 2);
#pragma unroll
            for (int t = 0; t < 8; t++) {
                int w = t * 8 + (lane & 3) * 2;
                *(__nv_bfloat162*)(sm + GE_A + c_loc * 144 + w * 2) =
                    __floats2bfloat162_rn(acc[t][0], acc[t][1]);
                *(__nv_bfloat162*)(sm + GE_A + (c_loc + 8) * 144 + w * 2) =
                    __floats2bfloat162_rn(acc[t][2], acc[t][3]);
                float sA = __expf(acc[t][0]) + __expf(acc[t][2]);
                float sB = __expf(acc[t][1]) + __expf(acc[t][3]);
                sA += __shfl_xor_sync(0xffffffffu, sA, 4);
                sB += __shfl_xor_sync(0xffffffffu, sB, 4);
                sA += __shfl_xor_sync(0xffffffffu, sA, 8);
                sB += __shfl_xor_sync(0xffffffffu, sB, 8);
                sA += __shfl_xor_sync(0xffffffffu, sA, 16);
                sB += __shfl_xor_sync(0xffffffffu, sB, 16);
                if (lane < 4) {
                    wred[(hj * 8 + wid) * 64 + w]     = sA;
                    wred[(hj * 8 + wid) * 64 + w + 1] = sB;
                }
            }
        }
        __syncthreads();
        // coalesced cp write: 128 c-rows x 128B
        {
            int cbase = cT * 128;
            for (int i = tid; i < 1024; i += 256) {
                int c = i >> 3, q = i & 7;
                uint4 v = *(const uint4*)(sm + GE_A + c * 144 + q * 16);
                *((uint4*)(g_cp + ((size_t)(b * 512 + cbase + c) * 64 + h) * 64) + q) = v;
            }
        }
        __syncthreads();
    }

    // final psum reduce
    {
        int hj = tid >> 6, w = tid & 63;
        float s = 0.f;
#pragma unroll
        for (int k = 0; k < 8; k++) s += wred[(hj * 8 + k) * 64 + w];
        g_psum[(((size_t)cT * 16 + b) * 64 + h0 + hj) * 64 + w] = s;
    }
}

// ---------------------------------------------------------------------------
// K4 (R5-proven layout): one-shot scalar stencil, 256 threads, 8c x 8w per
// thread, 2 CTAs/SM, weights 9/dhi from smem, inv hoisted before stencil.
// ---------------------------------------------------------------------------
#define CV_XT_F   (34 * 10 * 64)          // 21760 floats = 87040 B
#define CV_BYTES  (CV_XT_F * 4 + 256)

__global__ void __launch_bounds__(256, 2) k_conv(
    const float* __restrict__ x, const float* __restrict__ w3d,
    float* __restrict__ out) {
    extern __shared__ float xt[];   // [34 c][10 h][64 w]
    float* w3s = xt + CV_XT_F;      // [27]
    int h0 = blockIdx.x * 8;
    int c0 = blockIdx.y * 32;
    int b  = blockIdx.z;
    int tid = threadIdx.x;

    if (tid < 27) w3s[tid] = w3d[tid];

    // one-shot halo tile load via cp.async with zero-fill
    {
        unsigned dstb = s2u(xt);
        const float4* x4 = (const float4*)x;
        for (int i = tid; i < 5440; i += 256) {
            int w4 = i & 15, rest = i >> 4;
            int hi = rest % 10, ci = rest / 10;
            int cg = c0 - 1 + ci, hg = h0 - 1 + hi;
            bool ok = ((unsigned)cg < 512u) && ((unsigned)hg < 64u);
            const float4* src = ok ? (x4 + (((size_t)(b * 512 + cg) * 64 + hg) * 16 + w4)) : x4;
            int sz = ok ? 16 : 0;
            asm volatile("cp.async.cg.shared.global [%0], [%1], 16, %2;\n"
                         :: "r"(dstb + (unsigned)i * 16), "l"((const void*)src), "r"(sz));
        }
        asm volatile("cp.async.commit_group;\n" ::);
    }

    int wg = tid & 7, hq = (tid >> 3) & 7, cq = tid >> 6;  // cq 0..3, 8c each
    int h = h0 + hq;

    // hoist softmax denominators: LDG latency overlaps the tile wait + stencil
    float inv[8];
    {
        float4 s0 = make_float4(0.f, 0.f, 0.f, 0.f), s1 = s0;
#pragma unroll
        for (int ct = 0; ct < 4; ct++) {
            const float4* pp = (const float4*)(g_psum +
                (((size_t)ct * 16 + b) * 64 + h) * 64 + wg * 8);
            float4 p0 = pp[0], p1 = pp[1];
            s0.x += p0.x; s0.y += p0.y; s0.z += p0.z; s0.w += p0.w;
            s1.x += p1.x; s1.y += p1.y; s1.z += p1.z; s1.w += p1.w;
        }
        inv[0] = 1.f / s0.x; inv[1] = 1.f / s0.y; inv[2] = 1.f / s0.z; inv[3] = 1.f / s0.w;
        inv[4] = 1.f / s1.x; inv[5] = 1.f / s1.y; inv[6] = 1.f / s1.z; inv[7] = 1.f / s1.w;
    }

    asm volatile("cp.async.wait_group 0;\n" ::);
    __syncthreads();

    float res[8][8];
#pragma unroll
    for (int i = 0; i < 8; i++)
#pragma unroll
        for (int j = 0; j < 8; j++) res[i][j] = 0.f;

#pragma unroll
    for (int dhi = 0; dhi < 3; dhi++) {
        float wk[9];
#pragma unroll
        for (int t = 0; t < 9; t++) wk[t] = w3s[(t / 3) * 9 + dhi * 3 + (t % 3)];
#pragma unroll
        for (int ii = 0; ii < 10; ii++) {
            const float* row = xt + ((cq * 8 + ii) * 10 + (hq + dhi)) * 64 + wg * 8;
            float4 m0 = *(const float4*)row;
            float4 m1 = *(const float4*)(row + 4);
            float left  = (wg == 0) ? 0.f : row[-1];
            float right = (wg == 7) ? 0.f : row[8];
            float v[10] = {left, m0.x, m0.y, m0.z, m0.w,
                           m1.x, m1.y, m1.z, m1.w, right};
#pragma unroll
            for (int dc = 0; dc < 3; dc++) {
                int cc = ii - dc;
                if (cc < 0 || cc > 7) continue;
                float k0 = wk[dc * 3], k1 = wk[dc * 3 + 1], k2 = wk[dc * 3 + 2];
#pragma unroll
                for (int j = 0; j < 8; j++)
                    res[cc][j] += k0 * v[j] + k1 * v[j + 1] + k2 * v[j + 2];
            }
        }
    }

    // epilogue: o = res * exp(cp)*inv + x
#pragma unroll
    for (int cc = 0; cc < 8; cc++) {
        int c = c0 + cq * 8 + cc;
        const float* ctr = xt + ((cq * 8 + cc + 1) * 10 + (hq + 1)) * 64 + wg * 8;
        float4 xi0 = *(const float4*)ctr;
        float4 xi1 = *(const float4*)(ctr + 4);
        uint4 cv = *(const uint4*)(g_cp + ((size_t)(b * 512 + c) * 64 + h) * 64 + wg * 8);
        const __nv_bfloat162* cpp = (const __nv_bfloat162*)&cv;
        float xin[8] = {xi0.x, xi0.y, xi0.z, xi0.w, xi1.x, xi1.y, xi1.z, xi1.w};
        float o[8];
#pragma unroll
        for (int p = 0; p < 4; p++) {
            float2 cf = __bfloat1622float2(cpp[p]);
            o[2 * p]     = res[cc][2 * p]     * (__expf(cf.x) * inv[2 * p])     + xin[2 * p];
            o[2 * p + 1] = res[cc][2 * p + 1] * (__expf(cf.y) * inv[2 * p + 1]) + xin[2 * p + 1];
        }
        float* op = out + (((size_t)(b * 512 + c) * 64 + h) * 64 + wg * 8);
        *(float4*)(op)     = make_float4(o[0], o[1], o[2], o[3]);
        *(float4*)(op + 4) = make_float4(o[4], o[5], o[6], o[7]);
    }
}

// ---------------------------------------------------------------------------
extern "C" void kernel_launch(void* const* d_in, const int* in_sizes, int n_in,
                              void* d_out, int out_size) {
    const float* x   = (const float*)d_in[0];
    const float* w_c = (const float*)d_in[1];
    const float* a_c = (const float*)d_in[2];
    const float* w_w = (const float*)d_in[3];
    const float* a_w = (const float*)d_in[4];
    const float* w_h = (const float*)d_in[5];
    const float* a_h = (const float*)d_in[6];
    const float* w3d = (const float*)d_in[7];
    float* out = (float*)d_out;

    cudaFuncSetAttribute(k_gemmE, cudaFuncAttributeMaxDynamicSharedMemorySize, GE_BYTES);
    cudaFuncSetAttribute(k_conv, cudaFuncAttributeMaxDynamicSharedMemorySize, CV_BYTES);

    k_reduce<<<Bn * Cn, 256>>>(x);
    dim3 gridGap(Bn, 2);
    k_gap2<<<gridGap, 256>>>(w_w, a_w, w_h, a_h);
    dim3 gridG(4, 16, Bn);
    k_gemmE<<<gridG, 256, GE_BYTES>>>(w_c, a_c);
    dim3 gridC(8, 16, Bn);
    k_conv<<<gridC, 256, CV_BYTES>>>(x, w3d, out);
}

// round 14
// speedup vs baseline: 1.1298x; 1.1298x over previous
#include <cuda_runtime.h>
#include <cuda_bf16.h>
#include <cstdint>

#define Bn 16
#define Cn 512
#define Hn 64
#define Wn 64
#define Rn 64
#define A_LD 72    // bf16 row stride for A (144B)
#define GB_LD 264  // bf16 row stride for B tile (528B = 33x16B, conflict-free)

typedef unsigned long long ull;

// Scratch (device globals; no allocation allowed)
__device__ float g_sumC[Bn*Cn];
__device__ float g_partW[Bn*Cn*Wn];
__device__ float g_partH[Bn*Cn*Hn];
__device__ float g_wout[Bn*Rn*Wn];  // [b][r][w]
__device__ float g_hout[Bn*Rn*Hn];  // [b][r][h]
__device__ __align__(16) __nv_bfloat16 g_e[(size_t)Bn*Cn*Hn*Wn];  // exp(cp) bf16
__device__ float g_psum[4*Bn*Hn*Wn];  // partial exp-sums [cT][b][h][w]

__device__ __forceinline__ unsigned s2u(const void* p) {
    return (unsigned)__cvta_generic_to_shared(p);
}

// ---------------------------------------------------------------------------
// K1: per-(b,c) plane reductions
// ---------------------------------------------------------------------------
__global__ __launch_bounds__(256) void k_reduce(const float* __restrict__ x) {
    int plane = blockIdx.x;
    const float4* x4 = (const float4*)(x + (size_t)plane * 4096);
    int tid = threadIdx.x;

    __shared__ float4 s4[256];
    __shared__ float  sh[256][4];

    float4 wacc = make_float4(0.f, 0.f, 0.f, 0.f);
    float hacc[4];
#pragma unroll
    for (int k = 0; k < 4; k++) {
        float4 f = x4[tid + 256 * k];
        wacc.x += f.x; wacc.y += f.y; wacc.z += f.z; wacc.w += f.w;
        hacc[k] = f.x + f.y + f.z + f.w;
    }
    s4[tid] = wacc;
    sh[tid][0] = hacc[0]; sh[tid][1] = hacc[1];
    sh[tid][2] = hacc[2]; sh[tid][3] = hacc[3];
    __syncthreads();

    if (tid < 16) {
        float4 t = s4[tid];
#pragma unroll
        for (int j = 1; j < 16; j++) {
            float4 u = s4[tid + 16 * j];
            t.x += u.x; t.y += u.y; t.z += u.z; t.w += u.w;
        }
        ((float4*)g_partW)[plane * 16 + tid] = t;
        s4[tid] = t;
    }
    if (tid >= 64 && tid < 128) {
        int h = tid - 64;
        int base = (h & 15) * 16;
        int k = h >> 4;
        float s = 0.f;
#pragma unroll
        for (int j = 0; j < 16; j++) s += sh[base + j][k];
        g_partH[plane * 64 + h] = s;
    }
    __syncthreads();
    if (tid == 0) {
        float tot = 0.f;
#pragma unroll
        for (int j = 0; j < 16; j++) {
            float4 u = s4[j];
            tot += u.x + u.y + u.z + u.w;
        }
        g_sumC[plane] = tot;
    }
}

// ---------------------------------------------------------------------------
// K2: gap reductions + 3-tap branch conv + PReLU -> g_wout / g_hout.
// ---------------------------------------------------------------------------
__global__ __launch_bounds__(256) void k_gap2(
    const float* __restrict__ w_w, const float* __restrict__ a_w,
    const float* __restrict__ w_h, const float* __restrict__ a_h) {
    int b = blockIdx.x, sel = blockIdx.y;
    int tid = threadIdx.x;
    int w = tid & 63, part = tid >> 6;

    __shared__ float red[4][64];
    __shared__ float g[66];

    const float* src = sel ? g_partH : g_partW;
    const float* p = src + ((size_t)(b * 512 + part * 128)) * 64 + w;
    float s = 0.f;
#pragma unroll 8
    for (int c = 0; c < 128; c++) s += p[c * 64];
    red[part][w] = s;
    if (tid == 64 + 0) g[0] = 0.f;
    if (tid == 64 + 1) g[65] = 0.f;
    __syncthreads();
    if (tid < 64)
        g[tid + 1] = (red[0][tid] + red[1][tid] + red[2][tid] + red[3][tid]) * (1.f / 32768.f);
    __syncthreads();

    const float* wt = sel ? w_h : w_w;
    float av = sel ? a_h[0] : a_w[0];
    float* dst = (sel ? g_hout : g_wout) + (size_t)b * 4096;
    for (int i = tid; i < 4096; i += 256) {
        int r = i >> 6, w2 = i & 63;
        float v = wt[r * 3] * g[w2] + wt[r * 3 + 1] * g[w2 + 1] + wt[r * 3 + 2] * g[w2 + 2];
        dst[i] = (v >= 0.f) ? v : av * v;
    }
}

// ---------------------------------------------------------------------------
// K3: tiled MMA (A built in-block from g_sumC + w_c). Stores e = exp(cp) bf16
// (coalesced via smem staging) + partial exp-sums (psum).
// ---------------------------------------------------------------------------
#define GE_A    0        // bf16 [128][A_LD] = 18432 (A, then e staging)
#define GE_B    18432    // bf16 [64][GB_LD] = 33792
#define GE_WO   52224    // f32 [64][64] = 16384 ; reused as wred
#define GE_HO   68608    // f32 [64][4]  = 1024
#define GE_GC   69632    // f32 [132]
#define GE_WC   70160    // f32 [192]
#define GE_BYTES 71168

__global__ void __launch_bounds__(256) k_gemmE(
    const float* __restrict__ w_c, const float* __restrict__ a_c) {
    extern __shared__ char sm[];
    int cT = blockIdx.x, h0 = blockIdx.y * 4, b = blockIdx.z;
    int tid = threadIdx.x;
    int lane = tid & 31, wid = tid >> 5;

    float* wo_s = (float*)(sm + GE_WO);
    float* ho_s = (float*)(sm + GE_HO);
    float* gcs  = (float*)(sm + GE_GC);
    float* wcs  = (float*)(sm + GE_WC);

    {
        const float* sumC = g_sumC + b * 512;
        for (int i = tid; i < 130; i += 256) {
            int cg = cT * 128 - 1 + i;
            gcs[i] = ((unsigned)cg < 512u) ? sumC[cg] * (1.f / 4096.f) : 0.f;
        }
        if (tid < 192) wcs[tid] = w_c[tid];
        const float4* wsrc = (const float4*)(g_wout + (size_t)b * 4096);
        float4* wdst = (float4*)wo_s;
        for (int i = tid; i < 1024; i += 256) wdst[i] = wsrc[i];
        int r = tid >> 2, hh = tid & 3;
        ho_s[tid] = g_hout[(size_t)b * 4096 + r * 64 + h0 + hh];
    }
    __syncthreads();

    // build A tile bf16 [128 c][64 r] with PReLU
    {
        float av = a_c[0];
        __nv_bfloat16* A = (__nv_bfloat16*)(sm + GE_A);
        for (int i = tid; i < 4096; i += 256) {
            int c = i >> 5, r2 = (i & 31) * 2;
            float g0 = gcs[c], g1 = gcs[c + 1], g2 = gcs[c + 2];
            float v0 = wcs[r2 * 3] * g0 + wcs[r2 * 3 + 1] * g1 + wcs[r2 * 3 + 2] * g2;
            float v1 = wcs[r2 * 3 + 3] * g0 + wcs[r2 * 3 + 4] * g1 + wcs[r2 * 3 + 5] * g2;
            v0 = (v0 >= 0.f) ? v0 : av * v0;
            v1 = (v1 >= 0.f) ? v1 : av * v1;
            *(__nv_bfloat162*)(A + c * A_LD + r2) = __floats2bfloat162_rn(v0, v1);
        }
    }
    __syncthreads();

    // hoist A fragments (A smem dead afterwards)
    unsigned afr[4][4];
    {
        unsigned aBase = s2u(sm + GE_A);
        int cb = wid * 16;
        int aRow = lane & 15;
        unsigned aColOff = (unsigned)(lane >> 4) * 16u;
#pragma unroll
        for (int ks = 0; ks < 4; ks++) {
            unsigned ad = aBase + (unsigned)((cb + aRow) * A_LD + ks * 16) * 2u + aColOff;
            asm volatile("ldmatrix.sync.aligned.m8n8.x4.shared.b16 {%0,%1,%2,%3}, [%4];\n"
                         : "=r"(afr[ks][0]), "=r"(afr[ks][1]),
                           "=r"(afr[ks][2]), "=r"(afr[ks][3])
                         : "r"(ad));
        }
    }

    // build B once: B[r][hj*64+w] = ho[r][hj] * wo[r][w]
    {
        __nv_bfloat16* B = (__nv_bfloat16*)(sm + GE_B);
        for (int i = tid; i < 8192; i += 256) {
            int r = i >> 7, col = (i & 127) * 2;
            int hj = col >> 6, w = col & 63;
            float hv = ho_s[r * 4 + hj];
            *(__nv_bfloat162*)(B + r * GB_LD + col) =
                __floats2bfloat162_rn(hv * wo_s[r * 64 + w], hv * wo_s[r * 64 + w + 1]);
        }
    }
    __syncthreads();

    float* wred = wo_s;  // reuse (wo dead after B build)
    unsigned sBase = s2u(sm + GE_B);
    int bRowOff = (lane & 7) + ((lane & 8) ? 8 : 0);
    int bColOff = (lane & 16) ? 8 : 0;

    for (int hj = 0; hj < 4; hj++) {
        int h = h0 + hj;
        float acc[8][4];
#pragma unroll
        for (int t = 0; t < 8; t++)
#pragma unroll
            for (int q = 0; q < 4; q++) acc[t][q] = 0.f;

#pragma unroll
        for (int ks = 0; ks < 4; ks++) {
            int k0 = ks * 16;
#pragma unroll
            for (int nb = 0; nb < 4; nb++) {
                unsigned bd = sBase +
                    (unsigned)((k0 + bRowOff) * GB_LD + hj * 64 + nb * 16 + bColOff) * 2u;
                unsigned bq0, bq1, bq2, bq3;
                asm volatile("ldmatrix.sync.aligned.m8n8.x4.trans.shared.b16 {%0,%1,%2,%3}, [%4];\n"
                             : "=r"(bq0), "=r"(bq1), "=r"(bq2), "=r"(bq3) : "r"(bd));
                asm volatile(
                    "mma.sync.aligned.m16n8k16.row.col.f32.bf16.bf16.f32 "
                    "{%0,%1,%2,%3},{%4,%5,%6,%7},{%8,%9},{%0,%1,%2,%3};\n"
                    : "+f"(acc[2 * nb][0]), "+f"(acc[2 * nb][1]),
                      "+f"(acc[2 * nb][2]), "+f"(acc[2 * nb][3])
                    : "r"(afr[ks][0]), "r"(afr[ks][1]), "r"(afr[ks][2]), "r"(afr[ks][3]),
                      "r"(bq0), "r"(bq1));
                asm volatile(
                    "mma.sync.aligned.m16n8k16.row.col.f32.bf16.bf16.f32 "
                    "{%0,%1,%2,%3},{%4,%5,%6,%7},{%8,%9},{%0,%1,%2,%3};\n"
                    : "+f"(acc[2 * nb + 1][0]), "+f"(acc[2 * nb + 1][1]),
                      "+f"(acc[2 * nb + 1][2]), "+f"(acc[2 * nb + 1][3])
                    : "r"(afr[ks][0]), "r"(afr[ks][1]), "r"(afr[ks][2]), "r"(afr[ks][3]),
                      "r"(bq2), "r"(bq3));
            }
        }

        // stage e = exp(cp) bf16 into dead A region + warp psum partials
        {
            int c_loc = wid * 16 + (lane >> 2);
#pragma unroll
            for (int t = 0; t < 8; t++) {
                int w = t * 8 + (lane & 3) * 2;
                float e0 = __expf(acc[t][0]);
                float e1 = __expf(acc[t][1]);
                float e2 = __expf(acc[t][2]);
                float e3 = __expf(acc[t][3]);
                *(__nv_bfloat162*)(sm + GE_A + c_loc * 144 + w * 2) =
                    __floats2bfloat162_rn(e0, e1);
                *(__nv_bfloat162*)(sm + GE_A + (c_loc + 8) * 144 + w * 2) =
                    __floats2bfloat162_rn(e2, e3);
                float sA = e0 + e2;
                float sB = e1 + e3;
                sA += __shfl_xor_sync(0xffffffffu, sA, 4);
                sB += __shfl_xor_sync(0xffffffffu, sB, 4);
                sA += __shfl_xor_sync(0xffffffffu, sA, 8);
                sB += __shfl_xor_sync(0xffffffffu, sB, 8);
                sA += __shfl_xor_sync(0xffffffffu, sA, 16);
                sB += __shfl_xor_sync(0xffffffffu, sB, 16);
                if (lane < 4) {
                    wred[(hj * 8 + wid) * 64 + w]     = sA;
                    wred[(hj * 8 + wid) * 64 + w + 1] = sB;
                }
            }
        }
        __syncthreads();
        // coalesced e write: 128 c-rows x 128B
        {
            int cbase = cT * 128;
            for (int i = tid; i < 1024; i += 256) {
                int c = i >> 3, q = i & 7;
                uint4 v = *(const uint4*)(sm + GE_A + c * 144 + q * 16);
                *((uint4*)(g_e + ((size_t)(b * 512 + cbase + c) * 64 + h) * 64) + q) = v;
            }
        }
        __syncthreads();
    }

    // final psum reduce
    {
        int hj = tid >> 6, w = tid & 63;
        float s = 0.f;
#pragma unroll
        for (int k = 0; k < 8; k++) s += wred[(hj * 8 + k) * 64 + w];
        g_psum[(((size_t)cT * 16 + b) * 64 + h0 + hj) * 64 + w] = s;
    }
}

// ---------------------------------------------------------------------------
// K4 (R5 stencil verbatim, no MUFU): 256 thr, 8c x 8w per thread, one-shot
// tile, w3[27] in regs, inv computed after the stencil, o = res*(e*inv)+x.
// ---------------------------------------------------------------------------
#define CV_XT_F   (34 * 10 * 64)          // 21760 floats = 87040 B
#define CV_BYTES  (CV_XT_F * 4)

__global__ void __launch_bounds__(256, 2) k_conv(
    const float* __restrict__ x, const float* __restrict__ w3d,
    float* __restrict__ out) {
    extern __shared__ float xt[];   // [34 c][10 h][64 w]
    int h0 = blockIdx.x * 8;
    int c0 = blockIdx.y * 32;
    int b  = blockIdx.z;
    int tid = threadIdx.x;

    // one-shot halo tile load via cp.async with zero-fill
    {
        unsigned dstb = s2u(xt);
        const float4* x4 = (const float4*)x;
        for (int i = tid; i < 5440; i += 256) {
            int w4 = i & 15, rest = i >> 4;
            int hi = rest % 10, ci = rest / 10;
            int cg = c0 - 1 + ci, hg = h0 - 1 + hi;
            bool ok = ((unsigned)cg < 512u) && ((unsigned)hg < 64u);
            const float4* src = ok ? (x4 + (((size_t)(b * 512 + cg) * 64 + hg) * 16 + w4)) : x4;
            int sz = ok ? 16 : 0;
            asm volatile("cp.async.cg.shared.global [%0], [%1], 16, %2;\n"
                         :: "r"(dstb + (unsigned)i * 16), "l"((const void*)src), "r"(sz));
        }
        asm volatile("cp.async.commit_group;\n" ::);
        asm volatile("cp.async.wait_group 0;\n" ::);
    }
    __syncthreads();

    float w3[27];
#pragma unroll
    for (int t = 0; t < 27; t++) w3[t] = __ldg(w3d + t);
    int wg = tid & 7, hq = (tid >> 3) & 7, cq = tid >> 6;  // cq 0..3, 8c each
    int h = h0 + hq;

    float res[8][8];
#pragma unroll
    for (int i = 0; i < 8; i++)
#pragma unroll
        for (int j = 0; j < 8; j++) res[i][j] = 0.f;

    // input-stationary: each input row loaded once, feeds <=3 c-outs
#pragma unroll
    for (int ii = 0; ii < 10; ii++) {
#pragma unroll
        for (int dhi = 0; dhi < 3; dhi++) {
            const float* row = xt + ((cq * 8 + ii) * 10 + (hq + dhi)) * 64 + wg * 8;
            float4 m0 = *(const float4*)row;
            float4 m1 = *(const float4*)(row + 4);
            float left  = (wg == 0) ? 0.f : row[-1];
            float right = (wg == 7) ? 0.f : row[8];
            float v[10] = {left, m0.x, m0.y, m0.z, m0.w,
                           m1.x, m1.y, m1.z, m1.w, right};
#pragma unroll
            for (int dc = 0; dc < 3; dc++) {
                int cc = ii - dc;
                if (cc < 0 || cc > 7) continue;
                int t = (dc * 3 + dhi) * 3;
                float k0 = w3[t], k1 = w3[t + 1], k2 = w3[t + 2];
#pragma unroll
                for (int j = 0; j < 8; j++)
                    res[cc][j] += k0 * v[j] + k1 * v[j + 1] + k2 * v[j + 2];
            }
        }
    }

    // softmax denominators (after stencil: no live-range inflation)
    float inv[8];
    {
        float4 s0 = make_float4(0.f, 0.f, 0.f, 0.f), s1 = s0;
#pragma unroll
        for (int ct = 0; ct < 4; ct++) {
            const float4* pp = (const float4*)(g_psum +
                (((size_t)ct * 16 + b) * 64 + h) * 64 + wg * 8);
            float4 p0 = pp[0], p1 = pp[1];
            s0.x += p0.x; s0.y += p0.y; s0.z += p0.z; s0.w += p0.w;
            s1.x += p1.x; s1.y += p1.y; s1.z += p1.z; s1.w += p1.w;
        }
        inv[0] = 1.f / s0.x; inv[1] = 1.f / s0.y; inv[2] = 1.f / s0.z; inv[3] = 1.f / s0.w;
        inv[4] = 1.f / s1.x; inv[5] = 1.f / s1.y; inv[6] = 1.f / s1.z; inv[7] = 1.f / s1.w;
    }

    // epilogue: o = res * (e * inv) + x  (no MUFU)
#pragma unroll
    for (int cc = 0; cc < 8; cc++) {
        int c = c0 + cq * 8 + cc;
        const float* ctr = xt + ((cq * 8 + cc + 1) * 10 + (hq + 1)) * 64 + wg * 8;
        float4 xi0 = *(const float4*)ctr;
        float4 xi1 = *(const float4*)(ctr + 4);
        uint4 ev = *(const uint4*)(g_e + ((size_t)(b * 512 + c) * 64 + h) * 64 + wg * 8);
        const __nv_bfloat162* ep = (const __nv_bfloat162*)&ev;
        float xin[8] = {xi0.x, xi0.y, xi0.z, xi0.w, xi1.x, xi1.y, xi1.z, xi1.w};
        float o[8];
#pragma unroll
        for (int p = 0; p < 4; p++) {
            float2 ef = __bfloat1622float2(ep[p]);
            o[2 * p]     = res[cc][2 * p]     * (ef.x * inv[2 * p])     + xin[2 * p];
            o[2 * p + 1] = res[cc][2 * p + 1] * (ef.y * inv[2 * p + 1]) + xin[2 * p + 1];
        }
        float* op = out + (((size_t)(b * 512 + c) * 64 + h) * 64 + wg * 8);
        *(float4*)(op)     = make_float4(o[0], o[1], o[2], o[3]);
        *(float4*)(op + 4) = make_float4(o[4], o[5], o[6], o[7]);
    }
}

// ---------------------------------------------------------------------------
extern "C" void kernel_launch(void* const* d_in, const int* in_sizes, int n_in,
                              void* d_out, int out_size) {
    const float* x   = (const float*)d_in[0];
    const float* w_c = (const float*)d_in[1];
    const float* a_c = (const float*)d_in[2];
    const float* w_w = (const float*)d_in[3];
    const float* a_w = (const float*)d_in[4];
    const float* w_h = (const float*)d_in[5];
    const float* a_h = (const float*)d_in[6];
    const float* w3d = (const float*)d_in[7];
    float* out = (float*)d_out;

    cudaFuncSetAttribute(k_gemmE, cudaFuncAttributeMaxDynamicSharedMemorySize, GE_BYTES);
    cudaFuncSetAttribute(k_conv, cudaFuncAttributeMaxDynamicSharedMemorySize, CV_BYTES);

    k_reduce<<<Bn * Cn, 256>>>(x);
    dim3 gridGap(Bn, 2);
    k_gap2<<<gridGap, 256>>>(w_w, a_w, w_h, a_h);
    dim3 gridG(4, 16, Bn);
    k_gemmE<<<gridG, 256, GE_BYTES>>>(w_c, a_c);
    dim3 gridC(8, 16, Bn);
    k_conv<<<gridC, 256, CV_BYTES>>>(x, w3d, out);
}

// round 15
// speedup vs baseline: 1.1976x; 1.0600x over previous
#include <cuda_runtime.h>
#include <cuda_bf16.h>
#include <cstdint>

#define Bn 16
#define Cn 512
#define Hn 64
#define Wn 64
#define Rn 64
#define A_LD 72    // bf16 row stride for A (144B)
#define GB_LD 264  // bf16 row stride for B tile (528B = 33x16B, conflict-free)

typedef unsigned long long ull;

// Scratch (device globals; no allocation allowed)
__device__ float g_sumC[Bn*Cn];
__device__ float g_partW[Bn*Cn*Wn];
__device__ float g_partH[Bn*Cn*Hn];
__device__ float g_wout[Bn*Rn*Wn];  // [b][r][w]
__device__ float g_hout[Bn*Rn*Hn];  // [b][r][h]
__device__ __align__(16) __nv_bfloat16 g_e[(size_t)Bn*Cn*Hn*Wn];  // exp(cp) bf16
__device__ float g_psum[4*Bn*Hn*Wn];  // partial exp-sums [cT][b][h][w]
__device__ float g_inv[Bn*Hn*Wn];     // 1 / sum_c exp(cp)

__device__ __forceinline__ unsigned s2u(const void* p) {
    return (unsigned)__cvta_generic_to_shared(p);
}

// ---------------------------------------------------------------------------
// K1: per-(b,c) plane reductions
// ---------------------------------------------------------------------------
__global__ __launch_bounds__(256) void k_reduce(const float* __restrict__ x) {
    int plane = blockIdx.x;
    const float4* x4 = (const float4*)(x + (size_t)plane * 4096);
    int tid = threadIdx.x;

    __shared__ float4 s4[256];
    __shared__ float  sh[256][4];

    float4 wacc = make_float4(0.f, 0.f, 0.f, 0.f);
    float hacc[4];
#pragma unroll
    for (int k = 0; k < 4; k++) {
        float4 f = x4[tid + 256 * k];
        wacc.x += f.x; wacc.y += f.y; wacc.z += f.z; wacc.w += f.w;
        hacc[k] = f.x + f.y + f.z + f.w;
    }
    s4[tid] = wacc;
    sh[tid][0] = hacc[0]; sh[tid][1] = hacc[1];
    sh[tid][2] = hacc[2]; sh[tid][3] = hacc[3];
    __syncthreads();

    if (tid < 16) {
        float4 t = s4[tid];
#pragma unroll
        for (int j = 1; j < 16; j++) {
            float4 u = s4[tid + 16 * j];
            t.x += u.x; t.y += u.y; t.z += u.z; t.w += u.w;
        }
        ((float4*)g_partW)[plane * 16 + tid] = t;
        s4[tid] = t;
    }
    if (tid >= 64 && tid < 128) {
        int h = tid - 64;
        int base = (h & 15) * 16;
        int k = h >> 4;
        float s = 0.f;
#pragma unroll
        for (int j = 0; j < 16; j++) s += sh[base + j][k];
        g_partH[plane * 64 + h] = s;
    }
    __syncthreads();
    if (tid == 0) {
        float tot = 0.f;
#pragma unroll
        for (int j = 0; j < 16; j++) {
            float4 u = s4[j];
            tot += u.x + u.y + u.z + u.w;
        }
        g_sumC[plane] = tot;
    }
}

// ---------------------------------------------------------------------------
// K2: gap reductions + 3-tap branch conv + PReLU -> g_wout / g_hout.
// ---------------------------------------------------------------------------
__global__ __launch_bounds__(256) void k_gap2(
    const float* __restrict__ w_w, const float* __restrict__ a_w,
    const float* __restrict__ w_h, const float* __restrict__ a_h) {
    int b = blockIdx.x, sel = blockIdx.y;
    int tid = threadIdx.x;
    int w = tid & 63, part = tid >> 6;

    __shared__ float red[4][64];
    __shared__ float g[66];

    const float* src = sel ? g_partH : g_partW;
    const float* p = src + ((size_t)(b * 512 + part * 128)) * 64 + w;
    float s = 0.f;
#pragma unroll 8
    for (int c = 0; c < 128; c++) s += p[c * 64];
    red[part][w] = s;
    if (tid == 64 + 0) g[0] = 0.f;
    if (tid == 64 + 1) g[65] = 0.f;
    __syncthreads();
    if (tid < 64)
        g[tid + 1] = (red[0][tid] + red[1][tid] + red[2][tid] + red[3][tid]) * (1.f / 32768.f);
    __syncthreads();

    const float* wt = sel ? w_h : w_w;
    float av = sel ? a_h[0] : a_w[0];
    float* dst = (sel ? g_hout : g_wout) + (size_t)b * 4096;
    for (int i = tid; i < 4096; i += 256) {
        int r = i >> 6, w2 = i & 63;
        float v = wt[r * 3] * g[w2] + wt[r * 3 + 1] * g[w2 + 1] + wt[r * 3 + 2] * g[w2 + 2];
        dst[i] = (v >= 0.f) ? v : av * v;
    }
}

// ---------------------------------------------------------------------------
// K3: tiled MMA (A built in-block from g_sumC + w_c). Stores e = exp(cp) bf16
// (coalesced via smem staging) + partial exp-sums (psum).
// ---------------------------------------------------------------------------
#define GE_A    0        // bf16 [128][A_LD] = 18432 (A, then e staging)
#define GE_B    18432    // bf16 [64][GB_LD] = 33792
#define GE_WO   52224    // f32 [64][64] = 16384 ; reused as wred
#define GE_HO   68608    // f32 [64][4]  = 1024
#define GE_GC   69632    // f32 [132]
#define GE_WC   70160    // f32 [192]
#define GE_BYTES 71168

__global__ void __launch_bounds__(256) k_gemmE(
    const float* __restrict__ w_c, const float* __restrict__ a_c) {
    extern __shared__ char sm[];
    int cT = blockIdx.x, h0 = blockIdx.y * 4, b = blockIdx.z;
    int tid = threadIdx.x;
    int lane = tid & 31, wid = tid >> 5;

    float* wo_s = (float*)(sm + GE_WO);
    float* ho_s = (float*)(sm + GE_HO);
    float* gcs  = (float*)(sm + GE_GC);
    float* wcs  = (float*)(sm + GE_WC);

    {
        const float* sumC = g_sumC + b * 512;
        for (int i = tid; i < 130; i += 256) {
            int cg = cT * 128 - 1 + i;
            gcs[i] = ((unsigned)cg < 512u) ? sumC[cg] * (1.f / 4096.f) : 0.f;
        }
        if (tid < 192) wcs[tid] = w_c[tid];
        const float4* wsrc = (const float4*)(g_wout + (size_t)b * 4096);
        float4* wdst = (float4*)wo_s;
        for (int i = tid; i < 1024; i += 256) wdst[i] = wsrc[i];
        int r = tid >> 2, hh = tid & 3;
        ho_s[tid] = g_hout[(size_t)b * 4096 + r * 64 + h0 + hh];
    }
    __syncthreads();

    // build A tile bf16 [128 c][64 r] with PReLU
    {
        float av = a_c[0];
        __nv_bfloat16* A = (__nv_bfloat16*)(sm + GE_A);
        for (int i = tid; i < 4096; i += 256) {
            int c = i >> 5, r2 = (i & 31) * 2;
            float g0 = gcs[c], g1 = gcs[c + 1], g2 = gcs[c + 2];
            float v0 = wcs[r2 * 3] * g0 + wcs[r2 * 3 + 1] * g1 + wcs[r2 * 3 + 2] * g2;
            float v1 = wcs[r2 * 3 + 3] * g0 + wcs[r2 * 3 + 4] * g1 + wcs[r2 * 3 + 5] * g2;
            v0 = (v0 >= 0.f) ? v0 : av * v0;
            v1 = (v1 >= 0.f) ? v1 : av * v1;
            *(__nv_bfloat162*)(A + c * A_LD + r2) = __floats2bfloat162_rn(v0, v1);
        }
    }
    __syncthreads();

    // hoist A fragments (A smem dead afterwards)
    unsigned afr[4][4];
    {
        unsigned aBase = s2u(sm + GE_A);
        int cb = wid * 16;
        int aRow = lane & 15;
        unsigned aColOff = (unsigned)(lane >> 4) * 16u;
#pragma unroll
        for (int ks = 0; ks < 4; ks++) {
            unsigned ad = aBase + (unsigned)((cb + aRow) * A_LD + ks * 16) * 2u + aColOff;
            asm volatile("ldmatrix.sync.aligned.m8n8.x4.shared.b16 {%0,%1,%2,%3}, [%4];\n"
                         : "=r"(afr[ks][0]), "=r"(afr[ks][1]),
                           "=r"(afr[ks][2]), "=r"(afr[ks][3])
                         : "r"(ad));
        }
    }

    // build B once: B[r][hj*64+w] = ho[r][hj] * wo[r][w]
    {
        __nv_bfloat16* B = (__nv_bfloat16*)(sm + GE_B);
        for (int i = tid; i < 8192; i += 256) {
            int r = i >> 7, col = (i & 127) * 2;
            int hj = col >> 6, w = col & 63;
            float hv = ho_s[r * 4 + hj];
            *(__nv_bfloat162*)(B + r * GB_LD + col) =
                __floats2bfloat162_rn(hv * wo_s[r * 64 + w], hv * wo_s[r * 64 + w + 1]);
        }
    }
    __syncthreads();

    float* wred = wo_s;  // reuse (wo dead after B build)
    unsigned sBase = s2u(sm + GE_B);
    int bRowOff = (lane & 7) + ((lane & 8) ? 8 : 0);
    int bColOff = (lane & 16) ? 8 : 0;

    for (int hj = 0; hj < 4; hj++) {
        int h = h0 + hj;
        float acc[8][4];
#pragma unroll
        for (int t = 0; t < 8; t++)
#pragma unroll
            for (int q = 0; q < 4; q++) acc[t][q] = 0.f;

#pragma unroll
        for (int ks = 0; ks < 4; ks++) {
            int k0 = ks * 16;
#pragma unroll
            for (int nb = 0; nb < 4; nb++) {
                unsigned bd = sBase +
                    (unsigned)((k0 + bRowOff) * GB_LD + hj * 64 + nb * 16 + bColOff) * 2u;
                unsigned bq0, bq1, bq2, bq3;
                asm volatile("ldmatrix.sync.aligned.m8n8.x4.trans.shared.b16 {%0,%1,%2,%3}, [%4];\n"
                             : "=r"(bq0), "=r"(bq1), "=r"(bq2), "=r"(bq3) : "r"(bd));
                asm volatile(
                    "mma.sync.aligned.m16n8k16.row.col.f32.bf16.bf16.f32 "
                    "{%0,%1,%2,%3},{%4,%5,%6,%7},{%8,%9},{%0,%1,%2,%3};\n"
                    : "+f"(acc[2 * nb][0]), "+f"(acc[2 * nb][1]),
                      "+f"(acc[2 * nb][2]), "+f"(acc[2 * nb][3])
                    : "r"(afr[ks][0]), "r"(afr[ks][1]), "r"(afr[ks][2]), "r"(afr[ks][3]),
                      "r"(bq0), "r"(bq1));
                asm volatile(
                    "mma.sync.aligned.m16n8k16.row.col.f32.bf16.bf16.f32 "
                    "{%0,%1,%2,%3},{%4,%5,%6,%7},{%8,%9},{%0,%1,%2,%3};\n"
                    : "+f"(acc[2 * nb + 1][0]), "+f"(acc[2 * nb + 1][1]),
                      "+f"(acc[2 * nb + 1][2]), "+f"(acc[2 * nb + 1][3])
                    : "r"(afr[ks][0]), "r"(afr[ks][1]), "r"(afr[ks][2]), "r"(afr[ks][3]),
                      "r"(bq2), "r"(bq3));
            }
        }

        // stage e = exp(cp) bf16 into dead A region + warp psum partials
        {
            int c_loc = wid * 16 + (lane >> 2);
#pragma unroll
            for (int t = 0; t < 8; t++) {
                int w = t * 8 + (lane & 3) * 2;
                float e0 = __expf(acc[t][0]);
                float e1 = __expf(acc[t][1]);
                float e2 = __expf(acc[t][2]);
                float e3 = __expf(acc[t][3]);
                *(__nv_bfloat162*)(sm + GE_A + c_loc * 144 + w * 2) =
                    __floats2bfloat162_rn(e0, e1);
                *(__nv_bfloat162*)(sm + GE_A + (c_loc + 8) * 144 + w * 2) =
                    __floats2bfloat162_rn(e2, e3);
                float sA = e0 + e2;
                float sB = e1 + e3;
                sA += __shfl_xor_sync(0xffffffffu, sA, 4);
                sB += __shfl_xor_sync(0xffffffffu, sB, 4);
                sA += __shfl_xor_sync(0xffffffffu, sA, 8);
                sB += __shfl_xor_sync(0xffffffffu, sB, 8);
                sA += __shfl_xor_sync(0xffffffffu, sA, 16);
                sB += __shfl_xor_sync(0xffffffffu, sB, 16);
                if (lane < 4) {
                    wred[(hj * 8 + wid) * 64 + w]     = sA;
                    wred[(hj * 8 + wid) * 64 + w + 1] = sB;
                }
            }
        }
        __syncthreads();
        // coalesced e write: 128 c-rows x 128B
        {
            int cbase = cT * 128;
            for (int i = tid; i < 1024; i += 256) {
                int c = i >> 3, q = i & 7;
                uint4 v = *(const uint4*)(sm + GE_A + c * 144 + q * 16);
                *((uint4*)(g_e + ((size_t)(b * 512 + cbase + c) * 64 + h) * 64) + q) = v;
            }
        }
        __syncthreads();
    }

    // final psum reduce
    {
        int hj = tid >> 6, w = tid & 63;
        float s = 0.f;
#pragma unroll
        for (int k = 0; k < 8; k++) s += wred[(hj * 8 + k) * 64 + w];
        g_psum[(((size_t)cT * 16 + b) * 64 + h0 + hj) * 64 + w] = s;
    }
}

// ---------------------------------------------------------------------------
// K3b: tiny kernel: inv[b][h][w] = 1 / sum_cT psum
// ---------------------------------------------------------------------------
__global__ __launch_bounds__(256) void k_inv(int dummy) {
    int idx = blockIdx.x * 256 + threadIdx.x;   // [b][h][w], 65536 total
    float s = g_psum[idx] + g_psum[65536 + idx] +
              g_psum[2 * 65536 + idx] + g_psum[3 * 65536 + idx];
    g_inv[idx] = 1.f / s;
}

// ---------------------------------------------------------------------------
// K4: one-shot stencil, 256 thr, 4c x 2h x 8w per thread (24 row-loads / 64
// outputs), scalar FFMA, epilogue o = res*(e*inv)+x with precomputed inv.
// ---------------------------------------------------------------------------
#define CV_XT_F   (34 * 10 * 64)          // 21760 floats = 87040 B
#define CV_BYTES  (CV_XT_F * 4)

__global__ void __launch_bounds__(256, 2) k_conv(
    const float* __restrict__ x, const float* __restrict__ w3d,
    float* __restrict__ out) {
    extern __shared__ float xt[];   // [34 c][10 h][64 w]
    int h0 = blockIdx.x * 8;
    int c0 = blockIdx.y * 32;
    int b  = blockIdx.z;
    int tid = threadIdx.x;

    // one-shot halo tile load via cp.async with zero-fill
    {
        unsigned dstb = s2u(xt);
        const float4* x4 = (const float4*)x;
        for (int i = tid; i < 5440; i += 256) {
            int w4 = i & 15, rest = i >> 4;
            int hi = rest % 10, ci = rest / 10;
            int cg = c0 - 1 + ci, hg = h0 - 1 + hi;
            bool ok = ((unsigned)cg < 512u) && ((unsigned)hg < 64u);
            const float4* src = ok ? (x4 + (((size_t)(b * 512 + cg) * 64 + hg) * 16 + w4)) : x4;
            int sz = ok ? 16 : 0;
            asm volatile("cp.async.cg.shared.global [%0], [%1], 16, %2;\n"
                         :: "r"(dstb + (unsigned)i * 16), "l"((const void*)src), "r"(sz));
        }
        asm volatile("cp.async.commit_group;\n" ::);
        asm volatile("cp.async.wait_group 0;\n" ::);
    }
    __syncthreads();

    float w3[27];
#pragma unroll
    for (int t = 0; t < 27; t++) w3[t] = __ldg(w3d + t);
    int wg = tid & 7, hq = (tid >> 3) & 3, cq = tid >> 5;  // 4c x 2h per thread

    float res[4][2][8];
#pragma unroll
    for (int i = 0; i < 4; i++)
#pragma unroll
        for (int j = 0; j < 2; j++)
#pragma unroll
            for (int k = 0; k < 8; k++) res[i][j][k] = 0.f;

    // input-stationary: 24 distinct rows, each feeds <=3 dc x <=2 hh outputs
#pragma unroll
    for (int ci = 0; ci < 6; ci++) {
#pragma unroll
        for (int hi = 0; hi < 4; hi++) {
            const float* row = xt + ((cq * 4 + ci) * 10 + (hq * 2 + hi)) * 64 + wg * 8;
            float4 m0 = *(const float4*)row;
            float4 m1 = *(const float4*)(row + 4);
            float left  = (wg == 0) ? 0.f : row[-1];
            float right = (wg == 7) ? 0.f : row[8];
            float v[10] = {left, m0.x, m0.y, m0.z, m0.w,
                           m1.x, m1.y, m1.z, m1.w, right};
#pragma unroll
            for (int dc = 0; dc < 3; dc++) {
                int cc = ci - dc;
                if (cc < 0 || cc > 3) continue;
#pragma unroll
                for (int dh = 0; dh < 3; dh++) {
                    int hh = hi - dh;
                    if (hh < 0 || hh > 1) continue;
                    int t = (dc * 3 + dh) * 3;
                    float k0 = w3[t], k1 = w3[t + 1], k2 = w3[t + 2];
#pragma unroll
                    for (int j = 0; j < 8; j++)
                        res[cc][hh][j] += k0 * v[j] + k1 * v[j + 1] + k2 * v[j + 2];
                }
            }
        }
    }

    // epilogue: o = res * (e * inv) + x  (inv precomputed by k_inv)
#pragma unroll
    for (int hh = 0; hh < 2; hh++) {
        int h = h0 + hq * 2 + hh;
        const float4* ip = (const float4*)(g_inv + ((size_t)b * 64 + h) * 64 + wg * 8);
        float4 i0 = ip[0], i1 = ip[1];
        float inv[8] = {i0.x, i0.y, i0.z, i0.w, i1.x, i1.y, i1.z, i1.w};
#pragma unroll
        for (int cc = 0; cc < 4; cc++) {
            int c = c0 + cq * 4 + cc;
            const float* ctr = xt + ((cq * 4 + cc + 1) * 10 + (hq * 2 + hh + 1)) * 64 + wg * 8;
            float4 xi0 = *(const float4*)ctr;
            float4 xi1 = *(const float4*)(ctr + 4);
            uint4 ev = *(const uint4*)(g_e + ((size_t)(b * 512 + c) * 64 + h) * 64 + wg * 8);
            const __nv_bfloat162* ep = (const __nv_bfloat162*)&ev;
            float xin[8] = {xi0.x, xi0.y, xi0.z, xi0.w, xi1.x, xi1.y, xi1.z, xi1.w};
            float o[8];
#pragma unroll
            for (int p = 0; p < 4; p++) {
                float2 ef = __bfloat1622float2(ep[p]);
                o[2 * p]     = res[cc][hh][2 * p]     * (ef.x * inv[2 * p])     + xin[2 * p];
                o[2 * p + 1] = res[cc][hh][2 * p + 1] * (ef.y * inv[2 * p + 1]) + xin[2 * p + 1];
            }
            float* op = out + (((size_t)(b * 512 + c) * 64 + h) * 64 + wg * 8);
            *(float4*)(op)     = make_float4(o[0], o[1], o[2], o[3]);
            *(float4*)(op + 4) = make_float4(o[4], o[5], o[6], o[7]);
        }
    }
}

// ---------------------------------------------------------------------------
extern "C" void kernel_launch(void* const* d_in, const int* in_sizes, int n_in,
                              void* d_out, int out_size) {
    const float* x   = (const float*)d_in[0];
    const float* w_c = (const float*)d_in[1];
    const float* a_c = (const float*)d_in[2];
    const float* w_w = (const float*)d_in[3];
    const float* a_w = (const float*)d_in[4];
    const float* w_h = (const float*)d_in[5];
    const float* a_h = (const float*)d_in[6];
    const float* w3d = (const float*)d_in[7];
    float* out = (float*)d_out;

    cudaFuncSetAttribute(k_gemmE, cudaFuncAttributeMaxDynamicSharedMemorySize, GE_BYTES);
    cudaFuncSetAttribute(k_conv, cudaFuncAttributeMaxDynamicSharedMemorySize, CV_BYTES);

    k_reduce<<<Bn * Cn, 256>>>(x);
    dim3 gridGap(Bn, 2);
    k_gap2<<<gridGap, 256>>>(w_w, a_w, w_h, a_h);
    dim3 gridG(4, 16, Bn);
    k_gemmE<<<gridG, 256, GE_BYTES>>>(w_c, a_c);
    k_inv<<<256, 256>>>(0);
    dim3 gridC(8, 16, Bn);
    k_conv<<<gridC, 256, CV_BYTES>>>(x, w3d, out);
}

// round 16
// speedup vs baseline: 1.2070x; 1.0079x over previous
#include <cuda_runtime.h>
#include <cuda_bf16.h>
#include <cstdint>

#define Bn 16
#define Cn 512
#define Hn 64
#define Wn 64
#define Rn 64
#define A_LD 72    // bf16 row stride for A (144B)
#define GB_LD 264  // bf16 row stride for B tile (528B = 33x16B, conflict-free)

typedef unsigned long long ull;

// Scratch (device globals; no allocation allowed)
__device__ float g_sumC[Bn*Cn];
__device__ float g_partW[Bn*Cn*Wn];
__device__ float g_partH[Bn*Cn*Hn];
__device__ float g_wout[Bn*Rn*Wn];  // [b][r][w]
__device__ float g_hout[Bn*Rn*Hn];  // [b][r][h]
__device__ __align__(16) __nv_bfloat16 g_e[(size_t)Bn*Cn*Hn*Wn];  // exp(cp) bf16
__device__ float g_psum[4*Bn*Hn*Wn];  // partial exp-sums [cT][b][h][w]
__device__ float g_inv[Bn*Hn*Wn];     // 1 / sum_c exp(cp)
__device__ int   g_cnt[Bn*16];        // completion counters (zero-init, self-reset)

__device__ __forceinline__ unsigned s2u(const void* p) {
    return (unsigned)__cvta_generic_to_shared(p);
}

// ---------------------------------------------------------------------------
// K1 v2: 2 planes per block, 8 independent LDG.128 per thread (MLP=8)
// ---------------------------------------------------------------------------
__global__ __launch_bounds__(256) void k_reduce(const float* __restrict__ x) {
    int plane0 = blockIdx.x * 2;
    int tid = threadIdx.x;

    __shared__ float4 s4[2][256];
    __shared__ float  sh[2][256][4];

    float4 f[2][4];
#pragma unroll
    for (int p = 0; p < 2; p++) {
        const float4* x4 = (const float4*)(x + (size_t)(plane0 + p) * 4096);
#pragma unroll
        for (int k = 0; k < 4; k++) f[p][k] = x4[tid + 256 * k];
    }
#pragma unroll
    for (int p = 0; p < 2; p++) {
        float4 wacc = make_float4(0.f, 0.f, 0.f, 0.f);
#pragma unroll
        for (int k = 0; k < 4; k++) {
            wacc.x += f[p][k].x; wacc.y += f[p][k].y;
            wacc.z += f[p][k].z; wacc.w += f[p][k].w;
            sh[p][tid][k] = f[p][k].x + f[p][k].y + f[p][k].z + f[p][k].w;
        }
        s4[p][tid] = wacc;
    }
    __syncthreads();

    if (tid < 32) {
        int p = tid >> 4, j0 = tid & 15;
        float4 t = s4[p][j0];
#pragma unroll
        for (int j = 1; j < 16; j++) {
            float4 u = s4[p][j0 + 16 * j];
            t.x += u.x; t.y += u.y; t.z += u.z; t.w += u.w;
        }
        ((float4*)g_partW)[(plane0 + p) * 16 + j0] = t;
        s4[p][j0] = t;
    }
    if (tid >= 64 && tid < 192) {
        int rel = tid - 64;
        int p = rel >> 6, h = rel & 63;
        int base = (h & 15) * 16;
        int k = h >> 4;
        float s = 0.f;
#pragma unroll
        for (int j = 0; j < 16; j++) s += sh[p][base + j][k];
        g_partH[(plane0 + p) * 64 + h] = s;
    }
    __syncthreads();
    if (tid < 2) {
        float tot = 0.f;
#pragma unroll
        for (int j = 0; j < 16; j++) {
            float4 u = s4[tid][j];
            tot += u.x + u.y + u.z + u.w;
        }
        g_sumC[plane0 + tid] = tot;
    }
}

// ---------------------------------------------------------------------------
// K2: gap reductions + 3-tap branch conv + PReLU -> g_wout / g_hout.
// ---------------------------------------------------------------------------
__global__ __launch_bounds__(256) void k_gap2(
    const float* __restrict__ w_w, const float* __restrict__ a_w,
    const float* __restrict__ w_h, const float* __restrict__ a_h) {
    int b = blockIdx.x, sel = blockIdx.y;
    int tid = threadIdx.x;
    int w = tid & 63, part = tid >> 6;

    __shared__ float red[4][64];
    __shared__ float g[66];

    const float* src = sel ? g_partH : g_partW;
    const float* p = src + ((size_t)(b * 512 + part * 128)) * 64 + w;
    float s = 0.f;
#pragma unroll 8
    for (int c = 0; c < 128; c++) s += p[c * 64];
    red[part][w] = s;
    if (tid == 64 + 0) g[0] = 0.f;
    if (tid == 64 + 1) g[65] = 0.f;
    __syncthreads();
    if (tid < 64)
        g[tid + 1] = (red[0][tid] + red[1][tid] + red[2][tid] + red[3][tid]) * (1.f / 32768.f);
    __syncthreads();

    const float* wt = sel ? w_h : w_w;
    float av = sel ? a_h[0] : a_w[0];
    float* dst = (sel ? g_hout : g_wout) + (size_t)b * 4096;
    for (int i = tid; i < 4096; i += 256) {
        int r = i >> 6, w2 = i & 63;
        float v = wt[r * 3] * g[w2] + wt[r * 3 + 1] * g[w2 + 1] + wt[r * 3 + 2] * g[w2 + 2];
        dst[i] = (v >= 0.f) ? v : av * v;
    }
}

// ---------------------------------------------------------------------------
// K3: tiled MMA (A built in-block). Stores e = exp(cp) bf16 + psum; the last
// of the 4 cT blocks per (b, hGroup) also computes g_inv (counter pattern).
// ---------------------------------------------------------------------------
#define GE_A    0        // bf16 [128][A_LD] = 18432 (A, then e staging)
#define GE_B    18432    // bf16 [64][GB_LD] = 33792
#define GE_WO   52224    // f32 [64][64] = 16384 ; reused as wred
#define GE_HO   68608    // f32 [64][4]  = 1024
#define GE_GC   69632    // f32 [132]
#define GE_WC   70160    // f32 [192]
#define GE_BYTES 71168

__global__ void __launch_bounds__(256) k_gemmE(
    const float* __restrict__ w_c, const float* __restrict__ a_c) {
    extern __shared__ char sm[];
    __shared__ int sLast;
    int cT = blockIdx.x, h0 = blockIdx.y * 4, b = blockIdx.z;
    int tid = threadIdx.x;
    int lane = tid & 31, wid = tid >> 5;

    float* wo_s = (float*)(sm + GE_WO);
    float* ho_s = (float*)(sm + GE_HO);
    float* gcs  = (float*)(sm + GE_GC);
    float* wcs  = (float*)(sm + GE_WC);

    {
        const float* sumC = g_sumC + b * 512;
        for (int i = tid; i < 130; i += 256) {
            int cg = cT * 128 - 1 + i;
            gcs[i] = ((unsigned)cg < 512u) ? sumC[cg] * (1.f / 4096.f) : 0.f;
        }
        if (tid < 192) wcs[tid] = w_c[tid];
        const float4* wsrc = (const float4*)(g_wout + (size_t)b * 4096);
        float4* wdst = (float4*)wo_s;
        for (int i = tid; i < 1024; i += 256) wdst[i] = wsrc[i];
        int r = tid >> 2, hh = tid & 3;
        ho_s[tid] = g_hout[(size_t)b * 4096 + r * 64 + h0 + hh];
    }
    __syncthreads();

    // build A tile bf16 [128 c][64 r] with PReLU
    {
        float av = a_c[0];
        __nv_bfloat16* A = (__nv_bfloat16*)(sm + GE_A);
        for (int i = tid; i < 4096; i += 256) {
            int c = i >> 5, r2 = (i & 31) * 2;
            float g0 = gcs[c], g1 = gcs[c + 1], g2 = gcs[c + 2];
            float v0 = wcs[r2 * 3] * g0 + wcs[r2 * 3 + 1] * g1 + wcs[r2 * 3 + 2] * g2;
            float v1 = wcs[r2 * 3 + 3] * g0 + wcs[r2 * 3 + 4] * g1 + wcs[r2 * 3 + 5] * g2;
            v0 = (v0 >= 0.f) ? v0 : av * v0;
            v1 = (v1 >= 0.f) ? v1 : av * v1;
            *(__nv_bfloat162*)(A + c * A_LD + r2) = __floats2bfloat162_rn(v0, v1);
        }
    }
    __syncthreads();

    // hoist A fragments (A smem dead afterwards)
    unsigned afr[4][4];
    {
        unsigned aBase = s2u(sm + GE_A);
        int cb = wid * 16;
        int aRow = lane & 15;
        unsigned aColOff = (unsigned)(lane >> 4) * 16u;
#pragma unroll
        for (int ks = 0; ks < 4; ks++) {
            unsigned ad = aBase + (unsigned)((cb + aRow) * A_LD + ks * 16) * 2u + aColOff;
            asm volatile("ldmatrix.sync.aligned.m8n8.x4.shared.b16 {%0,%1,%2,%3}, [%4];\n"
                         : "=r"(afr[ks][0]), "=r"(afr[ks][1]),
                           "=r"(afr[ks][2]), "=r"(afr[ks][3])
                         : "r"(ad));
        }
    }

    // build B once: B[r][hj*64+w] = ho[r][hj] * wo[r][w]
    {
        __nv_bfloat16* B = (__nv_bfloat16*)(sm + GE_B);
        for (int i = tid; i < 8192; i += 256) {
            int r = i >> 7, col = (i & 127) * 2;
            int hj = col >> 6, w = col & 63;
            float hv = ho_s[r * 4 + hj];
            *(__nv_bfloat162*)(B + r * GB_LD + col) =
                __floats2bfloat162_rn(hv * wo_s[r * 64 + w], hv * wo_s[r * 64 + w + 1]);
        }
    }
    __syncthreads();

    float* wred = wo_s;  // reuse (wo dead after B build)
    unsigned sBase = s2u(sm + GE_B);
    int bRowOff = (lane & 7) + ((lane & 8) ? 8 : 0);
    int bColOff = (lane & 16) ? 8 : 0;

    for (int hj = 0; hj < 4; hj++) {
        int h = h0 + hj;
        float acc[8][4];
#pragma unroll
        for (int t = 0; t < 8; t++)
#pragma unroll
            for (int q = 0; q < 4; q++) acc[t][q] = 0.f;

#pragma unroll
        for (int ks = 0; ks < 4; ks++) {
            int k0 = ks * 16;
#pragma unroll
            for (int nb = 0; nb < 4; nb++) {
                unsigned bd = sBase +
                    (unsigned)((k0 + bRowOff) * GB_LD + hj * 64 + nb * 16 + bColOff) * 2u;
                unsigned bq0, bq1, bq2, bq3;
                asm volatile("ldmatrix.sync.aligned.m8n8.x4.trans.shared.b16 {%0,%1,%2,%3}, [%4];\n"
                             : "=r"(bq0), "=r"(bq1), "=r"(bq2), "=r"(bq3) : "r"(bd));
                asm volatile(
                    "mma.sync.aligned.m16n8k16.row.col.f32.bf16.bf16.f32 "
                    "{%0,%1,%2,%3},{%4,%5,%6,%7},{%8,%9},{%0,%1,%2,%3};\n"
                    : "+f"(acc[2 * nb][0]), "+f"(acc[2 * nb][1]),
                      "+f"(acc[2 * nb][2]), "+f"(acc[2 * nb][3])
                    : "r"(afr[ks][0]), "r"(afr[ks][1]), "r"(afr[ks][2]), "r"(afr[ks][3]),
                      "r"(bq0), "r"(bq1));
                asm volatile(
                    "mma.sync.aligned.m16n8k16.row.col.f32.bf16.bf16.f32 "
                    "{%0,%1,%2,%3},{%4,%5,%6,%7},{%8,%9},{%0,%1,%2,%3};\n"
                    : "+f"(acc[2 * nb + 1][0]), "+f"(acc[2 * nb + 1][1]),
                      "+f"(acc[2 * nb + 1][2]), "+f"(acc[2 * nb + 1][3])
                    : "r"(afr[ks][0]), "r"(afr[ks][1]), "r"(afr[ks][2]), "r"(afr[ks][3]),
                      "r"(bq2), "r"(bq3));
            }
        }

        // stage e = exp(cp) bf16 into dead A region + warp psum partials
        {
            int c_loc = wid * 16 + (lane >> 2);
#pragma unroll
            for (int t = 0; t < 8; t++) {
                int w = t * 8 + (lane & 3) * 2;
                float e0 = __expf(acc[t][0]);
                float e1 = __expf(acc[t][1]);
                float e2 = __expf(acc[t][2]);
                float e3 = __expf(acc[t][3]);
                *(__nv_bfloat162*)(sm + GE_A + c_loc * 144 + w * 2) =
                    __floats2bfloat162_rn(e0, e1);
                *(__nv_bfloat162*)(sm + GE_A + (c_loc + 8) * 144 + w * 2) =
                    __floats2bfloat162_rn(e2, e3);
                float sA = e0 + e2;
                float sB = e1 + e3;
                sA += __shfl_xor_sync(0xffffffffu, sA, 4);
                sB += __shfl_xor_sync(0xffffffffu, sB, 4);
                sA += __shfl_xor_sync(0xffffffffu, sA, 8);
                sB += __shfl_xor_sync(0xffffffffu, sB, 8);
                sA += __shfl_xor_sync(0xffffffffu, sA, 16);
                sB += __shfl_xor_sync(0xffffffffu, sB, 16);
                if (lane < 4) {
                    wred[(hj * 8 + wid) * 64 + w]     = sA;
                    wred[(hj * 8 + wid) * 64 + w + 1] = sB;
                }
            }
        }
        __syncthreads();
        // coalesced e write: 128 c-rows x 128B
        {
            int cbase = cT * 128;
            for (int i = tid; i < 1024; i += 256) {
                int c = i >> 3, q = i & 7;
                uint4 v = *(const uint4*)(sm + GE_A + c * 144 + q * 16);
                *((uint4*)(g_e + ((size_t)(b * 512 + cbase + c) * 64 + h) * 64) + q) = v;
            }
        }
        __syncthreads();
    }

    // final psum reduce
    {
        int hj = tid >> 6, w = tid & 63;
        float s = 0.f;
#pragma unroll
        for (int k = 0; k < 8; k++) s += wred[(hj * 8 + k) * 64 + w];
        g_psum[(((size_t)cT * 16 + b) * 64 + h0 + hj) * 64 + w] = s;
    }
    __syncthreads();

    // last of the 4 cT blocks for this (b, hGroup) computes g_inv
    if (tid == 0) {
        __threadfence();
        int done = atomicAdd(&g_cnt[b * 16 + blockIdx.y], 1);
        sLast = (done == 3);
    }
    __syncthreads();
    if (sLast) {
        int hj = tid >> 6, w = tid & 63;
        int idx = ((b * 64) + h0 + hj) * 64 + w;
        float s = g_psum[idx] + g_psum[65536 + idx] +
                  g_psum[2 * 65536 + idx] + g_psum[3 * 65536 + idx];
        g_inv[idx] = 1.f / s;
        if (tid == 0) g_cnt[b * 16 + blockIdx.y] = 0;   // reset for graph replay
    }
}

// ---------------------------------------------------------------------------
// K4: one-shot stencil, 256 thr, 4c x 2h x 8w per thread, scalar FFMA,
// epilogue o = res*(e*inv)+x with precomputed inv.
// ---------------------------------------------------------------------------
#define CV_XT_F   (34 * 10 * 64)          // 21760 floats = 87040 B
#define CV_BYTES  (CV_XT_F * 4)

__global__ void __launch_bounds__(256, 2) k_conv(
    const float* __restrict__ x, const float* __restrict__ w3d,
    float* __restrict__ out) {
    extern __shared__ float xt[];   // [34 c][10 h][64 w]
    int h0 = blockIdx.x * 8;
    int c0 = blockIdx.y * 32;
    int b  = blockIdx.z;
    int tid = threadIdx.x;

    // one-shot halo tile load via cp.async with zero-fill
    {
        unsigned dstb = s2u(xt);
        const float4* x4 = (const float4*)x;
        for (int i = tid; i < 5440; i += 256) {
            int w4 = i & 15, rest = i >> 4;
            int hi = rest % 10, ci = rest / 10;
            int cg = c0 - 1 + ci, hg = h0 - 1 + hi;
            bool ok = ((unsigned)cg < 512u) && ((unsigned)hg < 64u);
            const float4* src = ok ? (x4 + (((size_t)(b * 512 + cg) * 64 + hg) * 16 + w4)) : x4;
            int sz = ok ? 16 : 0;
            asm volatile("cp.async.cg.shared.global [%0], [%1], 16, %2;\n"
                         :: "r"(dstb + (unsigned)i * 16), "l"((const void*)src), "r"(sz));
        }
        asm volatile("cp.async.commit_group;\n" ::);
        asm volatile("cp.async.wait_group 0;\n" ::);
    }
    __syncthreads();

    float w3[27];
#pragma unroll
    for (int t = 0; t < 27; t++) w3[t] = __ldg(w3d + t);
    int wg = tid & 7, hq = (tid >> 3) & 3, cq = tid >> 5;  // 4c x 2h per thread

    float res[4][2][8];
#pragma unroll
    for (int i = 0; i < 4; i++)
#pragma unroll
        for (int j = 0; j < 2; j++)
#pragma unroll
            for (int k = 0; k < 8; k++) res[i][j][k] = 0.f;

    // input-stationary: 24 distinct rows, each feeds <=3 dc x <=2 hh outputs
#pragma unroll
    for (int ci = 0; ci < 6; ci++) {
#pragma unroll
        for (int hi = 0; hi < 4; hi++) {
            const float* row = xt + ((cq * 4 + ci) * 10 + (hq * 2 + hi)) * 64 + wg * 8;
            float4 m0 = *(const float4*)row;
            float4 m1 = *(const float4*)(row + 4);
            float left  = (wg == 0) ? 0.f : row[-1];
            float right = (wg == 7) ? 0.f : row[8];
            float v[10] = {left, m0.x, m0.y, m0.z, m0.w,
                           m1.x, m1.y, m1.z, m1.w, right};
#pragma unroll
            for (int dc = 0; dc < 3; dc++) {
                int cc = ci - dc;
                if (cc < 0 || cc > 3) continue;
#pragma unroll
                for (int dh = 0; dh < 3; dh++) {
                    int hh = hi - dh;
                    if (hh < 0 || hh > 1) continue;
                    int t = (dc * 3 + dh) * 3;
                    float k0 = w3[t], k1 = w3[t + 1], k2 = w3[t + 2];
#pragma unroll
                    for (int j = 0; j < 8; j++)
                        res[cc][hh][j] += k0 * v[j] + k1 * v[j + 1] + k2 * v[j + 2];
                }
            }
        }
    }

    // epilogue: o = res * (e * inv) + x  (inv precomputed)
#pragma unroll
    for (int hh = 0; hh < 2; hh++) {
        int h = h0 + hq * 2 + hh;
        const float4* ip = (const float4*)(g_inv + ((size_t)b * 64 + h) * 64 + wg * 8);
        float4 i0 = ip[0], i1 = ip[1];
        float inv[8] = {i0.x, i0.y, i0.z, i0.w, i1.x, i1.y, i1.z, i1.w};
#pragma unroll
        for (int cc = 0; cc < 4; cc++) {
            int c = c0 + cq * 4 + cc;
            const float* ctr = xt + ((cq * 4 + cc + 1) * 10 + (hq * 2 + hh + 1)) * 64 + wg * 8;
            float4 xi0 = *(const float4*)ctr;
            float4 xi1 = *(const float4*)(ctr + 4);
            uint4 ev = *(const uint4*)(g_e + ((size_t)(b * 512 + c) * 64 + h) * 64 + wg * 8);
            const __nv_bfloat162* ep = (const __nv_bfloat162*)&ev;
            float xin[8] = {xi0.x, xi0.y, xi0.z, xi0.w, xi1.x, xi1.y, xi1.z, xi1.w};
            float o[8];
#pragma unroll
            for (int p = 0; p < 4; p++) {
                float2 ef = __bfloat1622float2(ep[p]);
                o[2 * p]     = res[cc][hh][2 * p]     * (ef.x * inv[2 * p])     + xin[2 * p];
                o[2 * p + 1] = res[cc][hh][2 * p + 1] * (ef.y * inv[2 * p + 1]) + xin[2 * p + 1];
            }
            float* op = out + (((size_t)(b * 512 + c) * 64 + h) * 64 + wg * 8);
            *(float4*)(op)     = make_float4(o[0], o[1], o[2], o[3]);
            *(float4*)(op + 4) = make_float4(o[4], o[5], o[6], o[7]);
        }
    }
}

// ---------------------------------------------------------------------------
extern "C" void kernel_launch(void* const* d_in, const int* in_sizes, int n_in,
                              void* d_out, int out_size) {
    const float* x   = (const float*)d_in[0];
    const float* w_c = (const float*)d_in[1];
    const float* a_c = (const float*)d_in[2];
    const float* w_w = (const float*)d_in[3];
    const float* a_w = (const float*)d_in[4];
    const float* w_h = (const float*)d_in[5];
    const float* a_h = (const float*)d_in[6];
    const float* w3d = (const float*)d_in[7];
    float* out = (float*)d_out;

    cudaFuncSetAttribute(k_gemmE, cudaFuncAttributeMaxDynamicSharedMemorySize, GE_BYTES);
    cudaFuncSetAttribute(k_conv, cudaFuncAttributeMaxDynamicSharedMemorySize, CV_BYTES);

    k_reduce<<<Bn * Cn / 2, 256>>>(x);
    dim3 gridGap(Bn, 2);
    k_gap2<<<gridGap, 256>>>(w_w, a_w, w_h, a_h);
    dim3 gridG(4, 16, Bn);
    k_gemmE<<<gridG, 256, GE_BYTES>>>(w_c, a_c);
    dim3 gridC(8, 16, Bn);
    k_conv<<<gridC, 256, CV_BYTES>>>(x, w3d, out);
}